// round 2
// baseline (speedup 1.0000x reference)
#include <cuda_runtime.h>
#include <math.h>
#include <float.h>

#define OUTD    12
#define N_VOX   1728              // 12*12*12
#define N_ROIS  128
#define N_PTS   160000
#define NCH     64
#define KMAX    64                // cap on points per (roi,voxel); fallback handles overflow
#define NRV     (N_ROIS * N_VOX)  // 221184

#define TG      16                // tile grid is TG x TG over the xy scene
#define TILE_LO (-46.0f)
#define TILE_SZ (92.0f / TG)      // 5.75 m

// Scratch (__device__ globals = sanctioned scratch; zero-initialized at load).
__device__ int d_count[NRV];            // self-cleaned by pool_kernel each run
__device__ int d_list[NRV * KMAX];
__device__ int d_tile_cnt[TG * TG];     // OVERWRITTEN (not accumulated) each run
__device__ int d_tile_list[TG * TG][N_ROIS];

// ---------------------------------------------------------------------------
// Kernel 1: bin ROIs into xy tiles. One block per tile, one thread per ROI.
// Ballot-compaction -> deterministic ordered lists, no atomics, no zeroing.
// Edge tiles extend to +/-inf so every possible point position is covered.
// ---------------------------------------------------------------------------
__global__ __launch_bounds__(N_ROIS) void tile_bin_kernel(const float* __restrict__ rois)
{
    int tile = blockIdx.x;               // 0..255
    int t = threadIdx.x;                 // 0..127 (roi id)
    int tx = tile & (TG - 1), ty = tile >> 4;

    float x0 = TILE_LO + tx * TILE_SZ, x1 = x0 + TILE_SZ;
    float y0 = TILE_LO + ty * TILE_SZ, y1 = y0 + TILE_SZ;
    if (tx == 0)      x0 = -1e30f;
    if (tx == TG - 1) x1 =  1e30f;
    if (ty == 0)      y0 = -1e30f;
    if (ty == TG - 1) y1 =  1e30f;

    const float* R = rois + t * 7;
    float cx = R[0], cy = R[1];
    float hdx = R[3] * 0.5f, hdy = R[4] * 0.5f;
    float r2 = (hdx * hdx + hdy * hdy) * 1.0002f + 1e-6f;   // same margin as build
    float qx = fminf(fmaxf(cx, x0), x1) - cx;               // closest rect point - center
    float qy = fminf(fmaxf(cy, y0), y1) - cy;
    bool hit = (qx * qx + qy * qy) <= r2;

    __shared__ int woff[4];
    unsigned m = __ballot_sync(0xffffffffu, hit);
    int wid = t >> 5, lane = t & 31;
    if (lane == 0) woff[wid] = __popc(m);
    __syncthreads();
    if (t == 0) {
        int s = 0;
        for (int w = 0; w < 4; w++) { int c = woff[w]; woff[w] = s; s += c; }
        d_tile_cnt[tile] = s;            // overwrite: no zeroing dependency
    }
    __syncthreads();
    if (hit) {
        int pos = woff[wid] + __popc(m & ((1u << lane) - 1u));
        d_tile_list[tile][pos] = t;
    }
}

// ---------------------------------------------------------------------------
// Kernel 2: one thread per point. Only test ROIs binned to the point's tile
// (~2-6 candidates instead of 128). Exact reference predicate inside.
// ---------------------------------------------------------------------------
__global__ __launch_bounds__(256) void build_lists_kernel(
    const float* __restrict__ rois, const float* __restrict__ pts)
{
    __shared__ float4 sA[N_ROIS];  // {cx, cy, r2_margin, cz}
    __shared__ float4 sB[N_ROIS];  // {cosa, sina, hdx, hdy}
    __shared__ float4 sC[N_ROIS];  // {hdz, vx, vy, vz}

    int t = threadIdx.x;
    if (t < N_ROIS) {
        const float* R = rois + t * 7;
        float cx = R[0], cy = R[1], cz = R[2];
        float dx = R[3], dy = R[4], dz = R[5];
        float ry = R[6];
        float hdx = dx * 0.5f, hdy = dy * 0.5f, hdz = dz * 0.5f;
        float r2  = (hdx * hdx + hdy * hdy) * 1.0002f + 1e-6f;
        float ca  = cosf(-ry), sa = sinf(-ry);
        sA[t] = make_float4(cx, cy, r2, cz);
        sB[t] = make_float4(ca, sa, hdx, hdy);
        sC[t] = make_float4(hdz, dx / (float)OUTD, dy / (float)OUTD, dz / (float)OUTD);
    }
    __syncthreads();

    int p = blockIdx.x * blockDim.x + t;
    if (p >= N_PTS) return;
    float px = pts[3 * p + 0];
    float py = pts[3 * p + 1];
    float pz = pts[3 * p + 2];

    int tx = min(TG - 1, max(0, (int)floorf((px - TILE_LO) * (1.0f / TILE_SZ))));
    int ty = min(TG - 1, max(0, (int)floorf((py - TILE_LO) * (1.0f / TILE_SZ))));
    int tile = ty * TG + tx;
    int cnt = d_tile_cnt[tile];
    const int* tl = d_tile_list[tile];

    for (int j = 0; j < cnt; j++) {
        int r = tl[j];
        float4 A = sA[r];
        float sx = px - A.x;
        float sy = py - A.y;
        float d2 = sx * sx + sy * sy;
        if (d2 > A.z) continue;                 // circle reject (conservative)

        float sz = pz - A.w;
        float4 B = sB[r];
        float4 C = sC[r];
        float lx = sx * B.x - sy * B.y;         // rotate into roi frame (angle = -ry)
        float ly = sx * B.y + sy * B.x;
        bool in_box = (lx > -B.z) && (lx < B.z) &&
                      (ly > -B.w) && (ly < B.w) &&
                      (fabsf(sz - C.x) <= C.x);
        if (!in_box) continue;

        int xi = min(OUTD - 1, max(0, (int)floorf((lx + B.z) / C.y)));
        int yi = min(OUTD - 1, max(0, (int)floorf((ly + B.w) / C.z)));
        int zi = min(OUTD - 1, max(0, (int)floorf(sz / C.w)));
        int rv = r * N_VOX + xi * (OUTD * OUTD) + yi * OUTD + zi;
        int c = atomicAdd(&d_count[rv], 1);
        if (c < KMAX) d_list[rv * KMAX + c] = p;
    }
}

// ---------------------------------------------------------------------------
// Kernel 3: one warp per (roi,voxel). Lane handles 2 channels (float2).
// Self-cleans d_count so no separate zeroing kernel is needed next run.
// ---------------------------------------------------------------------------
__global__ __launch_bounds__(256) void pool_kernel(
    const float* __restrict__ rois, const float* __restrict__ pts,
    const float* __restrict__ feat, float* __restrict__ out)
{
    int gtid = blockIdx.x * blockDim.x + threadIdx.x;
    int warp = gtid >> 5;
    int lane = threadIdx.x & 31;
    if (warp >= NRV) return;

    int n = d_count[warp];
    if (lane == 0) d_count[warp] = 0;   // restore invariant for next replay

    float2* o = (float2*)(out + (size_t)warp * NCH);
    if (n == 0) {
        o[lane] = make_float2(0.f, 0.f);
        return;
    }

    float mx0 = -FLT_MAX, mx1 = -FLT_MAX;
    int m = min(n, KMAX);
    const int* lst = &d_list[warp * KMAX];
    for (int j = 0; j < m; j++) {
        int pid = lst[j];                                     // warp-uniform load
        float2 v = ((const float2*)(feat + (size_t)pid * NCH))[lane];
        mx0 = fmaxf(mx0, v.x);
        mx1 = fmaxf(mx1, v.y);
    }

    if (n > KMAX) {
        // Correctness fallback (statistically never taken): rescan all points.
        int r = warp / N_VOX, vox = warp % N_VOX;
        int xi = vox / (OUTD * OUTD), yi = (vox / OUTD) % OUTD, zi = vox % OUTD;
        const float* R = rois + r * 7;
        float cx = R[0], cy = R[1], cz = R[2];
        float dx = R[3], dy = R[4], dz = R[5];
        float ry = R[6];
        float hdx = dx * 0.5f, hdy = dy * 0.5f, hdz = dz * 0.5f;
        float ca = cosf(-ry), sa = sinf(-ry);
        float vx = dx / (float)OUTD, vy = dy / (float)OUTD, vz = dz / (float)OUTD;
        for (int base = 0; base < N_PTS; base += 32) {
            int p = base + lane;
            bool hit = false;
            if (p < N_PTS) {
                float sx = pts[3 * p + 0] - cx;
                float sy = pts[3 * p + 1] - cy;
                float sz = pts[3 * p + 2] - cz;
                float lx = sx * ca - sy * sa;
                float ly = sx * sa + sy * ca;
                if ((lx > -hdx) && (lx < hdx) && (ly > -hdy) && (ly < hdy) &&
                    (fabsf(sz - hdz) <= hdz)) {
                    int xa = min(OUTD - 1, max(0, (int)floorf((lx + hdx) / vx)));
                    int ya = min(OUTD - 1, max(0, (int)floorf((ly + hdy) / vy)));
                    int za = min(OUTD - 1, max(0, (int)floorf(sz / vz)));
                    hit = (xa == xi) && (ya == yi) && (za == zi);
                }
            }
            unsigned mask = __ballot_sync(0xffffffffu, hit);
            while (mask) {
                int src = __ffs(mask) - 1;
                mask &= mask - 1;
                int pid = base + src;
                float2 v = ((const float2*)(feat + (size_t)pid * NCH))[lane];
                mx0 = fmaxf(mx0, v.x);
                mx1 = fmaxf(mx1, v.y);
            }
        }
    }
    o[lane] = make_float2(mx0, mx1);
}

// ---------------------------------------------------------------------------
extern "C" void kernel_launch(void* const* d_in, const int* in_sizes, int n_in,
                              void* d_out, int out_size)
{
    const float* rois = (const float*)d_in[0];       // (128, 7)
    const float* pts  = (const float*)d_in[1];       // (160000, 3)
    const float* feat = (const float*)d_in[2];       // (160000, 64)
    float* out = (float*)d_out;                      // (128, 12, 12, 12, 64)

    tile_bin_kernel<<<TG * TG, N_ROIS>>>(rois);
    build_lists_kernel<<<(N_PTS + 255) / 256, 256>>>(rois, pts);
    pool_kernel<<<NRV / 8, 256>>>(rois, pts, feat, out);  // 8 warps/block, 1 warp/(roi,voxel)
}